// round 1
// baseline (speedup 1.0000x reference)
#include <cuda_runtime.h>
#include <cstdint>
#include <cstddef>

// ---------------- problem constants (fixed shapes) ----------------
#define BATCH   4
#define SEQ     4096
#define DIM     1024
#define DINNER  1536
#define MROWS   (BATCH * SEQ)          // 16384

#define NSEG    32
#define SEGLEN  (SEQ / NSEG)           // 128

// ---------------- static device scratch (no allocs allowed) -------
__device__ float g_c[(size_t)MROWS * DINNER];   // coeff = 1 - z = sigmoid(-gate)
__device__ float g_v[(size_t)MROWS * DINNER];   // value = z * g(hidden)
__device__ float g_h[(size_t)MROWS * DINNER];   // scan output
__device__ float g_segA[BATCH * NSEG * DINNER]; // per-segment prod(c)
__device__ float g_segB[BATCH * NSEG * DINNER]; // per-segment value-only result
__device__ float g_hin[BATCH * NSEG * DINNER];  // h entering each segment

// ---------------- helpers -----------------------------------------
__device__ __forceinline__ uint32_t f2tf(float f) {
    uint32_t u;
    asm("cvt.rna.tf32.f32 %0, %1;" : "=r"(u) : "f"(f));
    return u;
}

__device__ __forceinline__ void mma_tf32(float& d0, float& d1, float& d2, float& d3,
                                         uint32_t a0, uint32_t a1, uint32_t a2, uint32_t a3,
                                         uint32_t b0, uint32_t b1) {
    asm volatile(
        "mma.sync.aligned.m16n8k8.row.col.f32.tf32.tf32.f32 "
        "{%0,%1,%2,%3},{%4,%5,%6,%7},{%8,%9},{%0,%1,%2,%3};\n"
        : "+f"(d0), "+f"(d1), "+f"(d2), "+f"(d3)
        : "r"(a0), "r"(a1), "r"(a2), "r"(a3), "r"(b0), "r"(b1));
}

__device__ __forceinline__ float sigmoidf_fast(float x) {
    return 1.0f / (1.0f + __expf(-x));
}

// ================================================================
// Kernel A: fused dual projection GEMM + gating epilogue.
// C_h = x @ W_hidden, C_g = x @ W_gate   (M=16384, K=1024, N=1536)
// epilogue writes c = sigmoid(-gate), v = sigmoid(gate)*g(hidden)
// Tiles: BM=128, BN=64 (per matrix), BK=16; 256 threads (8 warps: 4x2),
// warp tile 32x32 per matrix.
// ================================================================
__global__ void __launch_bounds__(256, 1)
k_proj_dual(const float* __restrict__ x,
            const float* __restrict__ Wh,
            const float* __restrict__ Wg)
{
    const int BM = 128, BN = 64, BK = 16;
    const int ASTR = 20;   // (lane>>2)*20 + (lane&3) -> 32 distinct banks
    const int BSTR = 72;   // (lane&3)*72 + (lane>>2) -> 32 distinct banks

    __shared__ uint32_t As[BM * ASTR];
    __shared__ uint32_t Bs[2][BK * BSTR];

    const int tid  = threadIdx.x;
    const int lane = tid & 31;
    const int wid  = tid >> 5;
    const int wm   = wid >> 1;   // 0..3 (M)
    const int wn   = wid & 1;    // 0..1 (N)

    const int row0 = blockIdx.x * BM;
    const int col0 = blockIdx.y * BN;

    float acc[2][2][4][4];
    #pragma unroll
    for (int a = 0; a < 2; a++)
        #pragma unroll
        for (int b = 0; b < 2; b++)
            #pragma unroll
            for (int c = 0; c < 4; c++)
                #pragma unroll
                for (int d = 0; d < 4; d++) acc[a][b][c][d] = 0.0f;

    const int a_row = tid >> 1;        // 0..127
    const int a_c4  = (tid & 1) * 2;   // float4 index 0 or 2
    const int b_row = tid >> 4;        // 0..15
    const int b_c4  = tid & 15;        // 0..15

    for (int k0 = 0; k0 < DIM; k0 += BK) {
        // --- load A tile (x) : 2 float4 per thread, tf32-round on store ---
        {
            const float4* xp = reinterpret_cast<const float4*>(
                x + (size_t)(row0 + a_row) * DIM + k0);
            float4 v0 = xp[a_c4 + 0];
            float4 v1 = xp[a_c4 + 1];
            uint32_t* as = &As[a_row * ASTR + a_c4 * 4];
            as[0] = f2tf(v0.x); as[1] = f2tf(v0.y); as[2] = f2tf(v0.z); as[3] = f2tf(v0.w);
            as[4] = f2tf(v1.x); as[5] = f2tf(v1.y); as[6] = f2tf(v1.z); as[7] = f2tf(v1.w);
        }
        // --- load B tiles (both weight matrices) : 1 float4 each ---
        {
            const float4* wp = reinterpret_cast<const float4*>(
                Wh + (size_t)(k0 + b_row) * DINNER + col0);
            float4 w = wp[b_c4];
            uint32_t* bs = &Bs[0][b_row * BSTR + b_c4 * 4];
            bs[0] = f2tf(w.x); bs[1] = f2tf(w.y); bs[2] = f2tf(w.z); bs[3] = f2tf(w.w);
        }
        {
            const float4* wp = reinterpret_cast<const float4*>(
                Wg + (size_t)(k0 + b_row) * DINNER + col0);
            float4 w = wp[b_c4];
            uint32_t* bs = &Bs[1][b_row * BSTR + b_c4 * 4];
            bs[0] = f2tf(w.x); bs[1] = f2tf(w.y); bs[2] = f2tf(w.z); bs[3] = f2tf(w.w);
        }
        __syncthreads();

        #pragma unroll
        for (int kk = 0; kk < BK; kk += 8) {
            uint32_t af[2][4];
            #pragma unroll
            for (int mt = 0; mt < 2; mt++) {
                int base = (wm * 32 + mt * 16 + (lane >> 2)) * ASTR + kk + (lane & 3);
                af[mt][0] = As[base];
                af[mt][1] = As[base + 8 * ASTR];
                af[mt][2] = As[base + 4];
                af[mt][3] = As[base + 8 * ASTR + 4];
            }
            #pragma unroll
            for (int mat = 0; mat < 2; mat++) {
                uint32_t bf[4][2];
                #pragma unroll
                for (int nt = 0; nt < 4; nt++) {
                    int bb = (kk + (lane & 3)) * BSTR + wn * 32 + nt * 8 + (lane >> 2);
                    bf[nt][0] = Bs[mat][bb];
                    bf[nt][1] = Bs[mat][bb + 4 * BSTR];
                }
                #pragma unroll
                for (int mt = 0; mt < 2; mt++)
                    #pragma unroll
                    for (int nt = 0; nt < 4; nt++)
                        mma_tf32(acc[mat][mt][nt][0], acc[mat][mt][nt][1],
                                 acc[mat][mt][nt][2], acc[mat][mt][nt][3],
                                 af[mt][0], af[mt][1], af[mt][2], af[mt][3],
                                 bf[nt][0], bf[nt][1]);
            }
        }
        __syncthreads();
    }

    // --- epilogue: gating nonlinearity, write c/v as float2 pairs ---
    #pragma unroll
    for (int mt = 0; mt < 2; mt++) {
        #pragma unroll
        for (int nt = 0; nt < 4; nt++) {
            int r = row0 + wm * 32 + mt * 16 + (lane >> 2);
            int c = col0 + wn * 32 + nt * 8 + (lane & 3) * 2;
            #pragma unroll
            for (int half = 0; half < 2; half++) {
                int rr = r + half * 8;
                float hid0 = acc[0][mt][nt][half * 2 + 0];
                float hid1 = acc[0][mt][nt][half * 2 + 1];
                float gat0 = acc[1][mt][nt][half * 2 + 0];
                float gat1 = acc[1][mt][nt][half * 2 + 1];
                float2 cw, vw;
                cw.x = sigmoidf_fast(-gat0);          // 1 - z, computed stably
                cw.y = sigmoidf_fast(-gat1);
                float z0 = sigmoidf_fast(gat0);
                float z1 = sigmoidf_fast(gat1);
                float gg0 = (hid0 >= 0.0f) ? (hid0 + 0.5f) : sigmoidf_fast(hid0);
                float gg1 = (hid1 >= 0.0f) ? (hid1 + 0.5f) : sigmoidf_fast(hid1);
                vw.x = z0 * gg0;
                vw.y = z1 * gg1;
                size_t idx = (size_t)rr * DINNER + c;
                *reinterpret_cast<float2*>(&g_c[idx]) = cw;
                *reinterpret_cast<float2*>(&g_v[idx]) = vw;
            }
        }
    }
}

// ================================================================
// Segmented linear scan:  h_t = c_t * h_{t-1} + v_t
// Phase 1: per (b, seg, channel) compute A=prod(c), B=recurrence from 0
// Phase 2: sequential combine of 32 segments per channel -> h_in per segment
// Phase 3: replay each segment from its h_in, writing per-step h
// ================================================================
__global__ void k_scan1()
{
    int f   = blockIdx.x * 128 + threadIdx.x;   // channel 0..1535
    int seg = blockIdx.y;
    int b   = blockIdx.z;
    size_t base = ((size_t)(b * SEQ + seg * SEGLEN)) * DINNER + f;
    float A = 1.0f, h = 0.0f;
    #pragma unroll 8
    for (int i = 0; i < SEGLEN; i++) {
        float c = g_c[base];
        float v = g_v[base];
        A *= c;
        h = fmaf(c, h, v);
        base += DINNER;
    }
    int sidx = (b * NSEG + seg) * DINNER + f;
    g_segA[sidx] = A;
    g_segB[sidx] = h;
}

__global__ void k_scan2()
{
    int idx = blockIdx.x * 256 + threadIdx.x;   // 0 .. BATCH*DINNER-1
    int b = idx / DINNER;
    int f = idx - b * DINNER;
    float h = 0.0f;
    #pragma unroll
    for (int seg = 0; seg < NSEG; seg++) {
        int sidx = (b * NSEG + seg) * DINNER + f;
        g_hin[sidx] = h;
        h = fmaf(g_segA[sidx], h, g_segB[sidx]);
    }
}

__global__ void k_scan3()
{
    int f   = blockIdx.x * 128 + threadIdx.x;
    int seg = blockIdx.y;
    int b   = blockIdx.z;
    size_t base = ((size_t)(b * SEQ + seg * SEGLEN)) * DINNER + f;
    float h = g_hin[(b * NSEG + seg) * DINNER + f];
    #pragma unroll 8
    for (int i = 0; i < SEGLEN; i++) {
        float c = g_c[base];
        float v = g_v[base];
        h = fmaf(c, h, v);
        g_h[base] = h;
        base += DINNER;
    }
}

// ================================================================
// Kernel C: output projection.  out = h @ W_out
// M=16384, K=1536, N=1024. Same tiling as kernel A, single matrix.
// ================================================================
__global__ void __launch_bounds__(256, 1)
k_out_gemm(const float* __restrict__ Wo, float* __restrict__ out)
{
    const int BM = 128, BN = 64, BK = 16;
    const int ASTR = 20;
    const int BSTR = 72;

    __shared__ uint32_t As[BM * ASTR];
    __shared__ uint32_t Bs[BK * BSTR];

    const int tid  = threadIdx.x;
    const int lane = tid & 31;
    const int wid  = tid >> 5;
    const int wm   = wid >> 1;
    const int wn   = wid & 1;

    const int row0 = blockIdx.x * BM;
    const int col0 = blockIdx.y * BN;

    float acc[2][4][4];
    #pragma unroll
    for (int b = 0; b < 2; b++)
        #pragma unroll
        for (int c = 0; c < 4; c++)
            #pragma unroll
            for (int d = 0; d < 4; d++) acc[b][c][d] = 0.0f;

    const int a_row = tid >> 1;
    const int a_c4  = (tid & 1) * 2;
    const int b_row = tid >> 4;
    const int b_c4  = tid & 15;

    for (int k0 = 0; k0 < DINNER; k0 += BK) {
        {
            const float4* hp = reinterpret_cast<const float4*>(
                g_h + (size_t)(row0 + a_row) * DINNER + k0);
            float4 v0 = hp[a_c4 + 0];
            float4 v1 = hp[a_c4 + 1];
            uint32_t* as = &As[a_row * ASTR + a_c4 * 4];
            as[0] = f2tf(v0.x); as[1] = f2tf(v0.y); as[2] = f2tf(v0.z); as[3] = f2tf(v0.w);
            as[4] = f2tf(v1.x); as[5] = f2tf(v1.y); as[6] = f2tf(v1.z); as[7] = f2tf(v1.w);
        }
        {
            const float4* wp = reinterpret_cast<const float4*>(
                Wo + (size_t)(k0 + b_row) * DIM + col0);
            float4 w = wp[b_c4];
            uint32_t* bs = &Bs[b_row * BSTR + b_c4 * 4];
            bs[0] = f2tf(w.x); bs[1] = f2tf(w.y); bs[2] = f2tf(w.z); bs[3] = f2tf(w.w);
        }
        __syncthreads();

        #pragma unroll
        for (int kk = 0; kk < BK; kk += 8) {
            uint32_t af[2][4];
            #pragma unroll
            for (int mt = 0; mt < 2; mt++) {
                int base = (wm * 32 + mt * 16 + (lane >> 2)) * ASTR + kk + (lane & 3);
                af[mt][0] = As[base];
                af[mt][1] = As[base + 8 * ASTR];
                af[mt][2] = As[base + 4];
                af[mt][3] = As[base + 8 * ASTR + 4];
            }
            uint32_t bf[4][2];
            #pragma unroll
            for (int nt = 0; nt < 4; nt++) {
                int bb = (kk + (lane & 3)) * BSTR + wn * 32 + nt * 8 + (lane >> 2);
                bf[nt][0] = Bs[bb];
                bf[nt][1] = Bs[bb + 4 * BSTR];
            }
            #pragma unroll
            for (int mt = 0; mt < 2; mt++)
                #pragma unroll
                for (int nt = 0; nt < 4; nt++)
                    mma_tf32(acc[mt][nt][0], acc[mt][nt][1],
                             acc[mt][nt][2], acc[mt][nt][3],
                             af[mt][0], af[mt][1], af[mt][2], af[mt][3],
                             bf[nt][0], bf[nt][1]);
        }
        __syncthreads();
    }

    #pragma unroll
    for (int mt = 0; mt < 2; mt++) {
        #pragma unroll
        for (int nt = 0; nt < 4; nt++) {
            int r = row0 + wm * 32 + mt * 16 + (lane >> 2);
            int c = col0 + wn * 32 + nt * 8 + (lane & 3) * 2;
            #pragma unroll
            for (int half = 0; half < 2; half++) {
                int rr = r + half * 8;
                float2 w;
                w.x = acc[mt][nt][half * 2 + 0];
                w.y = acc[mt][nt][half * 2 + 1];
                *reinterpret_cast<float2*>(&out[(size_t)rr * DIM + c]) = w;
            }
        }
    }
}

// ================================================================
// launch
// ================================================================
extern "C" void kernel_launch(void* const* d_in, const int* in_sizes, int n_in,
                              void* d_out, int out_size)
{
    const float* x  = (const float*)d_in[0];
    const float* Wh = (const float*)d_in[1];
    const float* Wg = (const float*)d_in[2];
    const float* Wo = (const float*)d_in[3];
    float* out = (float*)d_out;

    dim3 gA(MROWS / 128, DINNER / 64);        // 128 x 24
    k_proj_dual<<<gA, 256>>>(x, Wh, Wg);

    dim3 gS(DINNER / 128, NSEG, BATCH);       // 12 x 32 x 4 = 1536 blocks
    k_scan1<<<gS, 128>>>();
    k_scan2<<<(BATCH * DINNER) / 256, 256>>>();
    k_scan3<<<gS, 128>>>();

    dim3 gC(MROWS / 128, DIM / 64);           // 128 x 16
    k_out_gemm<<<gC, 256>>>(Wo, out);
}

// round 2
// speedup vs baseline: 1.2565x; 1.2565x over previous
#include <cuda_runtime.h>
#include <cstdint>
#include <cstddef>

// ---------------- problem constants ----------------
#define BATCH   4
#define SEQ     4096
#define DIM     1024
#define DINNER  1536
#define MROWS   (BATCH * SEQ)          // 16384

#define NSEG    64
#define SEGLEN  (SEQ / NSEG)           // 64

// ---------------- static device scratch ------------
__device__ float g_hid[(size_t)MROWS * DINNER];
__device__ float g_gat[(size_t)MROWS * DINNER];
__device__ float g_h  [(size_t)MROWS * DINNER];
__device__ float g_segA[BATCH * NSEG * DINNER];
__device__ float g_segB[BATCH * NSEG * DINNER];
__device__ float g_hin [BATCH * NSEG * DINNER];
__device__ float g_xtf[(size_t)MROWS * DIM];
__device__ float g_wh [DIM * DINNER];
__device__ float g_wg [DIM * DINNER];
__device__ float g_wo [DINNER * DIM];

// ---------------- helpers --------------------------
__device__ __forceinline__ uint32_t f2tf(float f) {
    uint32_t u;
    asm("cvt.rna.tf32.f32 %0, %1;" : "=r"(u) : "f"(f));
    return u;
}

__device__ __forceinline__ void mma_tf32(float& d0, float& d1, float& d2, float& d3,
                                         uint32_t a0, uint32_t a1, uint32_t a2, uint32_t a3,
                                         uint32_t b0, uint32_t b1) {
    asm volatile(
        "mma.sync.aligned.m16n8k8.row.col.f32.tf32.tf32.f32 "
        "{%0,%1,%2,%3},{%4,%5,%6,%7},{%8,%9},{%0,%1,%2,%3};\n"
        : "+f"(d0), "+f"(d1), "+f"(d2), "+f"(d3)
        : "r"(a0), "r"(a1), "r"(a2), "r"(a3), "r"(b0), "r"(b1));
}

__device__ __forceinline__ void cp16(float* s, const float* g) {
    uint32_t sa = (uint32_t)__cvta_generic_to_shared(s);
    asm volatile("cp.async.cg.shared.global [%0], [%1], 16;\n" :: "r"(sa), "l"(g));
}
__device__ __forceinline__ void cp_commit() {
    asm volatile("cp.async.commit_group;\n");
}
template<int N> __device__ __forceinline__ void cp_wait() {
    asm volatile("cp.async.wait_group %0;\n" :: "n"(N));
}

// ---------------- convert fp32 -> tf32-rounded fp32 ----------------
__global__ void k_cvt(const float4* __restrict__ in, float4* __restrict__ out, int n4)
{
    int i = blockIdx.x * 256 + threadIdx.x;
    if (i < n4) {
        float4 v = in[i];
        v.x = __uint_as_float(f2tf(v.x));
        v.y = __uint_as_float(f2tf(v.y));
        v.z = __uint_as_float(f2tf(v.z));
        v.w = __uint_as_float(f2tf(v.w));
        out[i] = v;
    }
}

// ================================================================
// Generic pipelined tf32 GEMM: C[M,N] = A[M,K] @ B[K,N]  (row-major)
// BM=128, BN=128, BK=16, 5-stage cp.async pipeline, 256 threads,
// 8 warps as 2(M)x4(N), warp tile 64x32.
// A,B must be pre-rounded to tf32 values (bits fed directly to mma).
// ================================================================
#define BK     16
#define STAGES 5
#define ASTR   20               // floats per A row in smem (conflict-free)
#define BSTR   136              // floats per B row in smem (conflict-free)
#define A_F    (128 * ASTR)     // 2560 floats per stage
#define B_F    (BK * BSTR)      // 2176 floats per stage
#define STG_F  (A_F + B_F)      // 4736 floats per stage
#define GEMM_SMEM (STAGES * STG_F * 4)

template<int KDIM, int NDIM>
__device__ __forceinline__ void load_stage(float* sm, int s, int k0,
                                           const float* __restrict__ A,
                                           const float* __restrict__ B,
                                           int row0, int col0, int tid)
{
    float* as = sm + s * STG_F;
    float* bs = as + A_F;
    #pragma unroll
    for (int i = 0; i < 2; i++) {
        int id  = tid + i * 256;
        int row = id >> 2;          // 0..127
        int c4  = id & 3;           // 0..3
        cp16(as + row * ASTR + c4 * 4,
             A + (size_t)(row0 + row) * KDIM + k0 + c4 * 4);
    }
    #pragma unroll
    for (int i = 0; i < 2; i++) {
        int id  = tid + i * 256;
        int row = id >> 5;          // 0..15
        int c4  = id & 31;          // 0..31
        cp16(bs + row * BSTR + c4 * 4,
             B + (size_t)(k0 + row) * NDIM + col0 + c4 * 4);
    }
}

__device__ __forceinline__ void compute_stage(const float* sm, int s,
                                              float (&acc)[4][4][4],
                                              int wm, int wn, int lane)
{
    const uint32_t* as = reinterpret_cast<const uint32_t*>(sm + s * STG_F);
    const uint32_t* bs = as + A_F;
    #pragma unroll
    for (int kk = 0; kk < BK; kk += 8) {
        uint32_t af[4][4];
        #pragma unroll
        for (int mt = 0; mt < 4; mt++) {
            int base = (wm * 64 + mt * 16 + (lane >> 2)) * ASTR + kk + (lane & 3);
            af[mt][0] = as[base];
            af[mt][1] = as[base + 8 * ASTR];
            af[mt][2] = as[base + 4];
            af[mt][3] = as[base + 8 * ASTR + 4];
        }
        uint32_t bf[4][2];
        #pragma unroll
        for (int nt = 0; nt < 4; nt++) {
            int bb = (kk + (lane & 3)) * BSTR + wn * 32 + nt * 8 + (lane >> 2);
            bf[nt][0] = bs[bb];
            bf[nt][1] = bs[bb + 4 * BSTR];
        }
        #pragma unroll
        for (int mt = 0; mt < 4; mt++)
            #pragma unroll
            for (int nt = 0; nt < 4; nt++)
                mma_tf32(acc[mt][nt][0], acc[mt][nt][1],
                         acc[mt][nt][2], acc[mt][nt][3],
                         af[mt][0], af[mt][1], af[mt][2], af[mt][3],
                         bf[nt][0], bf[nt][1]);
    }
}

template<int KDIM, int NDIM>
__global__ void __launch_bounds__(256, 1)
k_gemm(const float* __restrict__ A, const float* __restrict__ B,
       float* __restrict__ C)
{
    extern __shared__ float sm[];

    const int tid  = threadIdx.x;
    const int lane = tid & 31;
    const int wid  = tid >> 5;
    const int wm   = wid & 1;     // 0..1  (M, 64 rows each)
    const int wn   = wid >> 1;    // 0..3  (N, 32 cols each)

    const int row0 = blockIdx.x * 128;
    const int col0 = blockIdx.y * 128;

    float acc[4][4][4];
    #pragma unroll
    for (int a = 0; a < 4; a++)
        #pragma unroll
        for (int b = 0; b < 4; b++)
            #pragma unroll
            for (int c = 0; c < 4; c++) acc[a][b][c] = 0.0f;

    // prologue: fill STAGES-1 stages
    #pragma unroll
    for (int s = 0; s < STAGES - 1; s++) {
        load_stage<KDIM, NDIM>(sm, s, s * BK, A, B, row0, col0, tid);
        cp_commit();
    }
    cp_wait<STAGES - 2>();
    __syncthreads();

    const int KT = KDIM / BK;
    int rs = 0, ws = STAGES - 1;
    for (int kt = 0; kt < KT; kt++) {
        int kn = kt + STAGES - 1;
        if (kn < KT)
            load_stage<KDIM, NDIM>(sm, ws, kn * BK, A, B, row0, col0, tid);
        cp_commit();
        compute_stage(sm, rs, acc, wm, wn, lane);
        cp_wait<STAGES - 2>();
        __syncthreads();
        rs = (rs + 1 == STAGES) ? 0 : rs + 1;
        ws = (ws + 1 == STAGES) ? 0 : ws + 1;
    }

    // epilogue: plain store
    #pragma unroll
    for (int mt = 0; mt < 4; mt++) {
        #pragma unroll
        for (int nt = 0; nt < 4; nt++) {
            int r = row0 + wm * 64 + mt * 16 + (lane >> 2);
            int c = col0 + wn * 32 + nt * 8 + (lane & 3) * 2;
            #pragma unroll
            for (int half = 0; half < 2; half++) {
                float2 w;
                w.x = acc[mt][nt][half * 2 + 0];
                w.y = acc[mt][nt][half * 2 + 1];
                *reinterpret_cast<float2*>(&C[(size_t)(r + half * 8) * NDIM + c]) = w;
            }
        }
    }
}

// ================================================================
// Gating (recomputed on the fly) + segmented linear scan.
//   e = exp(gate); c = 1/(1+e); z = 1-c; v = z * g(hidden)
//   h_t = c_t * h_{t-1} + v_t
// ================================================================
__device__ __forceinline__ void gating(float hid, float gat, float& c, float& v)
{
    float e = __expf(gat);
    c = 1.0f / (1.0f + e);
    float z = 1.0f - c;
    float g = (hid >= 0.0f) ? (hid + 0.5f) : (1.0f / (1.0f + __expf(-hid)));
    v = z * g;
}

__global__ void k_scan1(const float* __restrict__ hid, const float* __restrict__ gat,
                        float* __restrict__ segA, float* __restrict__ segB)
{
    int f   = (blockIdx.x * 128 + threadIdx.x) * 2;
    int seg = blockIdx.y;
    int b   = blockIdx.z;
    size_t base = ((size_t)(b * SEQ + seg * SEGLEN)) * DINNER + f;
    float A0 = 1.0f, A1 = 1.0f, h0 = 0.0f, h1 = 0.0f;
    #pragma unroll 16
    for (int i = 0; i < SEGLEN; i++) {
        float2 hv = *reinterpret_cast<const float2*>(hid + base);
        float2 gv = *reinterpret_cast<const float2*>(gat + base);
        float c0, v0, c1, v1;
        gating(hv.x, gv.x, c0, v0);
        gating(hv.y, gv.y, c1, v1);
        A0 *= c0; h0 = fmaf(c0, h0, v0);
        A1 *= c1; h1 = fmaf(c1, h1, v1);
        base += DINNER;
    }
    int sidx = (b * NSEG + seg) * DINNER + f;
    *reinterpret_cast<float2*>(segA + sidx) = make_float2(A0, A1);
    *reinterpret_cast<float2*>(segB + sidx) = make_float2(h0, h1);
}

__global__ void k_scan2(const float* __restrict__ segA, const float* __restrict__ segB,
                        float* __restrict__ hin)
{
    int idx = blockIdx.x * 256 + threadIdx.x;   // 0 .. BATCH*DINNER-1
    int b = idx / DINNER;
    int f = idx - b * DINNER;
    float h = 0.0f;
    #pragma unroll
    for (int seg = 0; seg < NSEG; seg++) {
        int sidx = (b * NSEG + seg) * DINNER + f;
        hin[sidx] = h;
        h = fmaf(segA[sidx], h, segB[sidx]);
    }
}

__global__ void k_scan3(const float* __restrict__ hid, const float* __restrict__ gat,
                        const float* __restrict__ hin, float* __restrict__ hout)
{
    int f   = (blockIdx.x * 128 + threadIdx.x) * 2;
    int seg = blockIdx.y;
    int b   = blockIdx.z;
    size_t base = ((size_t)(b * SEQ + seg * SEGLEN)) * DINNER + f;
    float2 hv0 = *reinterpret_cast<const float2*>(hin + (b * NSEG + seg) * DINNER + f);
    float h0 = hv0.x, h1 = hv0.y;
    #pragma unroll 16
    for (int i = 0; i < SEGLEN; i++) {
        float2 hv = *reinterpret_cast<const float2*>(hid + base);
        float2 gv = *reinterpret_cast<const float2*>(gat + base);
        float c0, v0, c1, v1;
        gating(hv.x, gv.x, c0, v0);
        gating(hv.y, gv.y, c1, v1);
        h0 = fmaf(c0, h0, v0);
        h1 = fmaf(c1, h1, v1);
        // store tf32-pre-rounded so the out-GEMM can cp.async it directly
        float2 w;
        w.x = __uint_as_float(f2tf(h0));
        w.y = __uint_as_float(f2tf(h1));
        *reinterpret_cast<float2*>(hout + base) = w;
        base += DINNER;
    }
}

// ================================================================
// launch
// ================================================================
extern "C" void kernel_launch(void* const* d_in, const int* in_sizes, int n_in,
                              void* d_out, int out_size)
{
    const float* x  = (const float*)d_in[0];
    const float* Wh = (const float*)d_in[1];
    const float* Wg = (const float*)d_in[2];
    const float* Wo = (const float*)d_in[3];
    float* out = (float*)d_out;

    float *hid, *gat, *h, *sa, *sb, *hin, *xtf, *wh, *wg, *wo;
    cudaGetSymbolAddress((void**)&hid, g_hid);
    cudaGetSymbolAddress((void**)&gat, g_gat);
    cudaGetSymbolAddress((void**)&h,   g_h);
    cudaGetSymbolAddress((void**)&sa,  g_segA);
    cudaGetSymbolAddress((void**)&sb,  g_segB);
    cudaGetSymbolAddress((void**)&hin, g_hin);
    cudaGetSymbolAddress((void**)&xtf, g_xtf);
    cudaGetSymbolAddress((void**)&wh,  g_wh);
    cudaGetSymbolAddress((void**)&wg,  g_wg);
    cudaGetSymbolAddress((void**)&wo,  g_wo);

    cudaFuncSetAttribute(k_gemm<DIM, DINNER>,
                         cudaFuncAttributeMaxDynamicSharedMemorySize, GEMM_SMEM);
    cudaFuncSetAttribute(k_gemm<DINNER, DIM>,
                         cudaFuncAttributeMaxDynamicSharedMemorySize, GEMM_SMEM);

    // 1. pre-round inputs/weights to tf32 values
    {
        int n4 = (int)((size_t)MROWS * DIM / 4);
        k_cvt<<<(n4 + 255) / 256, 256>>>((const float4*)x, (float4*)xtf, n4);
        int w4 = DIM * DINNER / 4;
        k_cvt<<<(w4 + 255) / 256, 256>>>((const float4*)Wh, (float4*)wh, w4);
        k_cvt<<<(w4 + 255) / 256, 256>>>((const float4*)Wg, (float4*)wg, w4);
        k_cvt<<<(w4 + 255) / 256, 256>>>((const float4*)Wo, (float4*)wo, w4);
    }

    // 2. projections
    dim3 gP(MROWS / 128, DINNER / 128);       // 128 x 12
    k_gemm<DIM, DINNER><<<gP, 256, GEMM_SMEM>>>(xtf, wh, hid);
    k_gemm<DIM, DINNER><<<gP, 256, GEMM_SMEM>>>(xtf, wg, gat);

    // 3. segmented scan (gating fused)
    dim3 gS(DINNER / 256, NSEG, BATCH);       // 6 x 64 x 4
    k_scan1<<<gS, 128>>>(hid, gat, sa, sb);
    k_scan2<<<(BATCH * DINNER) / 256, 256>>>(sa, sb, hin);
    k_scan3<<<gS, 128>>>(hid, gat, hin, h);

    // 4. output projection
    dim3 gO(MROWS / 128, DIM / 128);          // 128 x 8
    k_gemm<DINNER, DIM><<<gO, 256, GEMM_SMEM>>>(h, wo, out);
}

// round 4
// speedup vs baseline: 2.0019x; 1.5933x over previous
#include <cuda_runtime.h>
#include <cuda_fp16.h>
#include <cstdint>
#include <cstddef>

// ---------------- problem constants ----------------
#define BATCH   4
#define SEQ     4096
#define DIM     1024
#define DINNER  1536
#define MROWS   (BATCH * SEQ)          // 16384

#define NSEG    64
#define SEGLEN  (SEQ / NSEG)           // 64

// ---------------- static device scratch ------------
__device__ __half g_hid[(size_t)MROWS * DINNER];
__device__ __half g_gat[(size_t)MROWS * DINNER];
__device__ __half g_h  [(size_t)MROWS * DINNER];
__device__ float  g_segA[BATCH * NSEG * DINNER];
__device__ float  g_segB[BATCH * NSEG * DINNER];
__device__ float  g_hin [BATCH * NSEG * DINNER];
__device__ __half g_xh [(size_t)MROWS * DIM];
__device__ __half g_wh [DIM * DINNER];   // transposed: [DINNER][DIM]
__device__ __half g_wg [DIM * DINNER];   // transposed: [DINNER][DIM]
__device__ __half g_wo [DINNER * DIM];   // transposed: [DIM][DINNER]

// ---------------- helpers --------------------------
__device__ __forceinline__ void mma_f16(float& d0, float& d1, float& d2, float& d3,
                                        uint32_t a0, uint32_t a1, uint32_t a2, uint32_t a3,
                                        uint32_t b0, uint32_t b1) {
    asm volatile(
        "mma.sync.aligned.m16n8k16.row.col.f32.f16.f16.f32 "
        "{%0,%1,%2,%3},{%4,%5,%6,%7},{%8,%9},{%0,%1,%2,%3};\n"
        : "+f"(d0), "+f"(d1), "+f"(d2), "+f"(d3)
        : "r"(a0), "r"(a1), "r"(a2), "r"(a3), "r"(b0), "r"(b1));
}

__device__ __forceinline__ void cp16(void* s, const void* g) {
    uint32_t sa = (uint32_t)__cvta_generic_to_shared(s);
    asm volatile("cp.async.cg.shared.global [%0], [%1], 16;\n" :: "r"(sa), "l"(g));
}
__device__ __forceinline__ void cp_commit() {
    asm volatile("cp.async.commit_group;\n");
}
template<int N> __device__ __forceinline__ void cp_wait() {
    asm volatile("cp.async.wait_group %0;\n" :: "n"(N));
}

// ---------------- convert fp32 -> fp16 ----------------
__global__ void k_cvt_h(const float4* __restrict__ in, __half2* __restrict__ out, int n4)
{
    int i = blockIdx.x * 256 + threadIdx.x;
    if (i < n4) {
        float4 v = in[i];
        out[2 * i + 0] = __floats2half2_rn(v.x, v.y);
        out[2 * i + 1] = __floats2half2_rn(v.z, v.w);
    }
}

// ---------------- transpose fp32 [R][C] -> fp16 [C][R] -----------
__global__ void k_transpose_h(const float* __restrict__ in, __half* __restrict__ out,
                              int R, int C)
{
    __shared__ float t[32][33];
    int x  = blockIdx.x * 32 + threadIdx.x;
    int y0 = blockIdx.y * 32 + threadIdx.y;
    #pragma unroll
    for (int i = 0; i < 32; i += 8)
        t[threadIdx.y + i][threadIdx.x] = in[(size_t)(y0 + i) * C + x];
    __syncthreads();
    int x2 = blockIdx.y * 32 + threadIdx.x;
    #pragma unroll
    for (int i = 0; i < 32; i += 8)
        out[(size_t)(blockIdx.x * 32 + threadIdx.y + i) * R + x2] =
            __float2half_rn(t[threadIdx.x][threadIdx.y + i]);
}

// ================================================================
// Pipelined fp16 GEMM:  C[M, ND] = A[M, KD] @ B[ND, KD]^T
// A: [M][KD] halves (k-contig).  B: pre-transposed [ND][KD] halves.
// BM=128, BN=128, BK=32 halves, 6-stage cp.async, 256 threads,
// 8 warps as 2(M)x4(N), warp tile 64x32. f32 accumulate.
// ================================================================
#define BKH     32                 // halves per K tile
#define RSTR    20                 // 32-bit words per smem row (16 payload + 4 pad)
#define ROWB    (RSTR * 4)         // 80 bytes per row
#define HALF_T  10240              // 128 rows * 80B (per operand)
#define STG_B   (2 * HALF_T)      // 20480 bytes per stage
#define STAGES  6
#define GEMM_SMEM (STAGES * STG_B)

template<int KD>
__device__ __forceinline__ void load_stage(char* smem, int s, int k0,
                                           const __half* __restrict__ A,
                                           const __half* __restrict__ B,
                                           int row0, int col0, int tid)
{
    char* sa = smem + s * STG_B;
    char* sb = sa + HALF_T;
    #pragma unroll
    for (int i = 0; i < 2; i++) {              // A: 512 chunks of 16B
        int id = tid + i * 256;
        int row = id >> 2, c = id & 3;
        cp16(sa + row * ROWB + c * 16, A + (size_t)(row0 + row) * KD + k0 + c * 8);
    }
    #pragma unroll
    for (int i = 0; i < 2; i++) {              // B: 512 chunks of 16B
        int id = tid + i * 256;
        int row = id >> 2, c = id & 3;
        cp16(sb + row * ROWB + c * 16, B + (size_t)(col0 + row) * KD + k0 + c * 8);
    }
}

__device__ __forceinline__ void compute_stage(const char* smem, int s,
                                              float (&acc)[4][4][4],
                                              int wm, int wn, int lane)
{
    const uint32_t* as = reinterpret_cast<const uint32_t*>(smem + s * STG_B);
    const uint32_t* bs = reinterpret_cast<const uint32_t*>(smem + s * STG_B + HALF_T);
    #pragma unroll
    for (int kk = 0; kk < 16; kk += 8) {       // two k16 groups (word units)
        uint32_t af[4][4];
        #pragma unroll
        for (int mt = 0; mt < 4; mt++) {
            int base = (wm * 64 + mt * 16 + (lane >> 2)) * RSTR + kk + (lane & 3);
            af[mt][0] = as[base];
            af[mt][1] = as[base + 8 * RSTR];
            af[mt][2] = as[base + 4];
            af[mt][3] = as[base + 8 * RSTR + 4];
        }
        uint32_t bf[4][2];
        #pragma unroll
        for (int nt = 0; nt < 4; nt++) {
            int bb = (wn * 32 + nt * 8 + (lane >> 2)) * RSTR + kk + (lane & 3);
            bf[nt][0] = bs[bb];
            bf[nt][1] = bs[bb + 4];
        }
        #pragma unroll
        for (int mt = 0; mt < 4; mt++)
            #pragma unroll
            for (int nt = 0; nt < 4; nt++)
                mma_f16(acc[mt][nt][0], acc[mt][nt][1],
                        acc[mt][nt][2], acc[mt][nt][3],
                        af[mt][0], af[mt][1], af[mt][2], af[mt][3],
                        bf[nt][0], bf[nt][1]);
    }
}

template<int KD, int ND, typename OutT>
__global__ void __launch_bounds__(256, 1)
k_gemm(const __half* __restrict__ A, const __half* __restrict__ B,
       OutT* __restrict__ C)
{
    extern __shared__ char smem[];

    const int tid  = threadIdx.x;
    const int lane = tid & 31;
    const int wid  = tid >> 5;
    const int wm   = wid & 1;     // 0..1  (M, 64 rows each)
    const int wn   = wid >> 1;    // 0..3  (N, 32 cols each)

    const int row0 = blockIdx.x * 128;
    const int col0 = blockIdx.y * 128;

    float acc[4][4][4];
    #pragma unroll
    for (int a = 0; a < 4; a++)
        #pragma unroll
        for (int b = 0; b < 4; b++)
            #pragma unroll
            for (int c = 0; c < 4; c++) acc[a][b][c] = 0.0f;

    #pragma unroll
    for (int s = 0; s < STAGES - 1; s++) {
        load_stage<KD>(smem, s, s * BKH, A, B, row0, col0, tid);
        cp_commit();
    }
    cp_wait<STAGES - 2>();
    __syncthreads();

    const int KT = KD / BKH;
    int rs = 0, ws = STAGES - 1;
    for (int kt = 0; kt < KT; kt++) {
        int kn = kt + STAGES - 1;
        if (kn < KT)
            load_stage<KD>(smem, ws, kn * BKH, A, B, row0, col0, tid);
        cp_commit();
        compute_stage(smem, rs, acc, wm, wn, lane);
        cp_wait<STAGES - 2>();
        __syncthreads();
        rs = (rs + 1 == STAGES) ? 0 : rs + 1;
        ws = (ws + 1 == STAGES) ? 0 : ws + 1;
    }

    // epilogue
    #pragma unroll
    for (int mt = 0; mt < 4; mt++) {
        #pragma unroll
        for (int nt = 0; nt < 4; nt++) {
            int r = row0 + wm * 64 + mt * 16 + (lane >> 2);
            int c = col0 + wn * 32 + nt * 8 + (lane & 3) * 2;
            #pragma unroll
            for (int half = 0; half < 2; half++) {
                float w0 = acc[mt][nt][half * 2 + 0];
                float w1 = acc[mt][nt][half * 2 + 1];
                size_t idx = (size_t)(r + half * 8) * ND + c;
                if constexpr (sizeof(OutT) == 2) {
                    *reinterpret_cast<__half2*>(
                        reinterpret_cast<__half*>(C) + idx) = __floats2half2_rn(w0, w1);
                } else {
                    *reinterpret_cast<float2*>(
                        reinterpret_cast<float*>(C) + idx) = make_float2(w0, w1);
                }
            }
        }
    }
}

// ================================================================
// Gating + segmented linear scan (fp16 in, fp16 h out)
//   e = exp(gate); c = 1/(1+e); z = 1-c; v = z * g(hidden)
//   h_t = c_t * h_{t-1} + v_t
// ================================================================
__device__ __forceinline__ void gating(float hid, float gat, float& c, float& v)
{
    float e = __expf(gat);
    c = 1.0f / (1.0f + e);
    float z = 1.0f - c;
    float g = (hid >= 0.0f) ? (hid + 0.5f) : (1.0f / (1.0f + __expf(-hid)));
    v = z * g;
}

#define D2 (DINNER / 2)            // 768 half2 per row

__global__ void k_scan1(const __half2* __restrict__ hid, const __half2* __restrict__ gat,
                        float* __restrict__ segA, float* __restrict__ segB)
{
    int f2  = blockIdx.x * 128 + threadIdx.x;   // 0..767
    int seg = blockIdx.y;
    int b   = blockIdx.z;
    size_t base = ((size_t)(b * SEQ + seg * SEGLEN)) * D2 + f2;
    float A0 = 1.0f, A1 = 1.0f, h0 = 0.0f, h1 = 0.0f;
    #pragma unroll 16
    for (int i = 0; i < SEGLEN; i++) {
        float2 hv = __half22float2(hid[base]);
        float2 gv = __half22float2(gat[base]);
        float c0, v0, c1, v1;
        gating(hv.x, gv.x, c0, v0);
        gating(hv.y, gv.y, c1, v1);
        A0 *= c0; h0 = fmaf(c0, h0, v0);
        A1 *= c1; h1 = fmaf(c1, h1, v1);
        base += D2;
    }
    int sidx = (b * NSEG + seg) * DINNER + f2 * 2;
    *reinterpret_cast<float2*>(segA + sidx) = make_float2(A0, A1);
    *reinterpret_cast<float2*>(segB + sidx) = make_float2(h0, h1);
}

__global__ void k_scan2(const float* __restrict__ segA, const float* __restrict__ segB,
                        float* __restrict__ hin)
{
    int idx = blockIdx.x * 256 + threadIdx.x;
    int b = idx / DINNER;
    int f = idx - b * DINNER;
    float h = 0.0f;
    #pragma unroll
    for (int seg = 0; seg < NSEG; seg++) {
        int sidx = (b * NSEG + seg) * DINNER + f;
        hin[sidx] = h;
        h = fmaf(segA[sidx], h, segB[sidx]);
    }
}

__global__ void k_scan3(const __half2* __restrict__ hid, const __half2* __restrict__ gat,
                        const float* __restrict__ hin, __half2* __restrict__ hout)
{
    int f2  = blockIdx.x * 128 + threadIdx.x;
    int seg = blockIdx.y;
    int b   = blockIdx.z;
    size_t base = ((size_t)(b * SEQ + seg * SEGLEN)) * D2 + f2;
    float2 hv0 = *reinterpret_cast<const float2*>(
        hin + (b * NSEG + seg) * DINNER + f2 * 2);
    float h0 = hv0.x, h1 = hv0.y;
    #pragma unroll 16
    for (int i = 0; i < SEGLEN; i++) {
        float2 hv = __half22float2(hid[base]);
        float2 gv = __half22float2(gat[base]);
        float c0, v0, c1, v1;
        gating(hv.x, gv.x, c0, v0);
        gating(hv.y, gv.y, c1, v1);
        h0 = fmaf(c0, h0, v0);
        h1 = fmaf(c1, h1, v1);
        hout[base] = __floats2half2_rn(h0, h1);
        base += D2;
    }
}

// ================================================================
// launch
// ================================================================
extern "C" void kernel_launch(void* const* d_in, const int* in_sizes, int n_in,
                              void* d_out, int out_size)
{
    const float* x  = (const float*)d_in[0];
    const float* Wh = (const float*)d_in[1];
    const float* Wg = (const float*)d_in[2];
    const float* Wo = (const float*)d_in[3];
    float* out = (float*)d_out;

    __half *hid, *gat, *h, *xh, *wh, *wg, *wo;
    float *sa, *sb, *hin;
    cudaGetSymbolAddress((void**)&hid, g_hid);
    cudaGetSymbolAddress((void**)&gat, g_gat);
    cudaGetSymbolAddress((void**)&h,   g_h);
    cudaGetSymbolAddress((void**)&sa,  g_segA);
    cudaGetSymbolAddress((void**)&sb,  g_segB);
    cudaGetSymbolAddress((void**)&hin, g_hin);
    cudaGetSymbolAddress((void**)&xh,  g_xh);
    cudaGetSymbolAddress((void**)&wh,  g_wh);
    cudaGetSymbolAddress((void**)&wg,  g_wg);
    cudaGetSymbolAddress((void**)&wo,  g_wo);

    cudaFuncSetAttribute(k_gemm<DIM, DINNER, __half>,
                         cudaFuncAttributeMaxDynamicSharedMemorySize, GEMM_SMEM);
    cudaFuncSetAttribute(k_gemm<DINNER, DIM, float>,
                         cudaFuncAttributeMaxDynamicSharedMemorySize, GEMM_SMEM);

    // 1. convert x to fp16; transpose weights to [N][K] fp16
    {
        int n4 = (int)((size_t)MROWS * DIM / 4);
        k_cvt_h<<<(n4 + 255) / 256, 256>>>((const float4*)x, (__half2*)xh, n4);
        dim3 tb(32, 8);
        k_transpose_h<<<dim3(DINNER / 32, DIM / 32), tb>>>(Wh, wh, DIM, DINNER);
        k_transpose_h<<<dim3(DINNER / 32, DIM / 32), tb>>>(Wg, wg, DIM, DINNER);
        k_transpose_h<<<dim3(DIM / 32, DINNER / 32), tb>>>(Wo, wo, DINNER, DIM);
    }

    // 2. projections
    dim3 gP(MROWS / 128, DINNER / 128);       // 128 x 12
    k_gemm<DIM, DINNER, __half><<<gP, 256, GEMM_SMEM>>>(xh, wh, hid);
    k_gemm<DIM, DINNER, __half><<<gP, 256, GEMM_SMEM>>>(xh, wg, gat);

    // 3. segmented scan (gating fused)
    dim3 gS(D2 / 128, NSEG, BATCH);           // 6 x 64 x 4
    k_scan1<<<gS, 128>>>((const __half2*)hid, (const __half2*)gat, sa, sb);
    k_scan2<<<(BATCH * DINNER) / 256, 256>>>(sa, sb, hin);
    k_scan3<<<gS, 128>>>((const __half2*)hid, (const __half2*)gat, hin, (__half2*)h);

    // 4. output projection
    dim3 gO(MROWS / 128, DIM / 128);          // 128 x 8
    k_gemm<DINNER, DIM, float><<<gO, 256, GEMM_SMEM>>>(h, wo, out);
}

// round 5
// speedup vs baseline: 2.4560x; 1.2268x over previous
#include <cuda_runtime.h>
#include <cuda_fp16.h>
#include <cstdint>
#include <cstddef>

// ---------------- problem constants ----------------
#define BATCH   4
#define SEQ     4096
#define DIM     1024
#define DINNER  1536
#define MROWS   (BATCH * SEQ)          // 16384
#define HGROW   (2 * DINNER)           // 3072 halves per hg row

#define NSEG    64
#define SEGLEN  (SEQ / NSEG)           // 64

// ---------------- static device scratch ------------
__device__ __half g_hg [(size_t)MROWS * HGROW];   // interleaved (hidden,gate)
__device__ __half g_h  [(size_t)MROWS * DINNER];
__device__ float  g_segA[BATCH * NSEG * DINNER];
__device__ float  g_segB[BATCH * NSEG * DINNER];
__device__ float  g_hin [BATCH * NSEG * DINNER];
__device__ __half g_xh [(size_t)MROWS * DIM];
__device__ __half g_whg[(size_t)HGROW * DIM];     // interleaved transposed weights
__device__ __half g_wo [DIM * DINNER];            // transposed: [DIM][DINNER]

// ---------------- helpers --------------------------
__device__ __forceinline__ void mma_f16(float& d0, float& d1, float& d2, float& d3,
                                        uint32_t a0, uint32_t a1, uint32_t a2, uint32_t a3,
                                        uint32_t b0, uint32_t b1) {
    asm volatile(
        "mma.sync.aligned.m16n8k16.row.col.f32.f16.f16.f32 "
        "{%0,%1,%2,%3},{%4,%5,%6,%7},{%8,%9},{%0,%1,%2,%3};\n"
        : "+f"(d0), "+f"(d1), "+f"(d2), "+f"(d3)
        : "r"(a0), "r"(a1), "r"(a2), "r"(a3), "r"(b0), "r"(b1));
}

__device__ __forceinline__ void ldsm4(uint32_t& r0, uint32_t& r1,
                                      uint32_t& r2, uint32_t& r3, uint32_t a) {
    asm volatile("ldmatrix.sync.aligned.m8n8.x4.shared.b16 {%0,%1,%2,%3}, [%4];"
                 : "=r"(r0), "=r"(r1), "=r"(r2), "=r"(r3) : "r"(a));
}

__device__ __forceinline__ void cp16(void* s, const void* g) {
    uint32_t sa = (uint32_t)__cvta_generic_to_shared(s);
    asm volatile("cp.async.cg.shared.global [%0], [%1], 16;\n" :: "r"(sa), "l"(g));
}
__device__ __forceinline__ void cp_commit() {
    asm volatile("cp.async.commit_group;\n");
}
template<int N> __device__ __forceinline__ void cp_wait() {
    asm volatile("cp.async.wait_group %0;\n" :: "n"(N));
}

// ---------------- convert fp32 -> fp16 ----------------
__global__ void k_cvt_h(const float4* __restrict__ in, __half2* __restrict__ out, int n4)
{
    int i = blockIdx.x * 256 + threadIdx.x;
    if (i < n4) {
        float4 v = in[i];
        out[2 * i + 0] = __floats2half2_rn(v.x, v.y);
        out[2 * i + 1] = __floats2half2_rn(v.z, v.w);
    }
}

// -------- transpose Wh,Wg [DIM][DINNER] f32 -> interleaved [2*DINNER][DIM] f16
__global__ void k_transpose_hg(const float* __restrict__ Wh, const float* __restrict__ Wg,
                               __half* __restrict__ out)
{
    __shared__ float th[32][33], tg[32][33];
    int x  = blockIdx.x * 32 + threadIdx.x;     // f
    int y0 = blockIdx.y * 32 + threadIdx.y;     // k
    #pragma unroll
    for (int i = 0; i < 32; i += 8) {
        th[threadIdx.y + i][threadIdx.x] = Wh[(size_t)(y0 + i) * DINNER + x];
        tg[threadIdx.y + i][threadIdx.x] = Wg[(size_t)(y0 + i) * DINNER + x];
    }
    __syncthreads();
    int k2 = blockIdx.y * 32 + threadIdx.x;     // k
    #pragma unroll
    for (int i = 0; i < 32; i += 8) {
        int f = blockIdx.x * 32 + threadIdx.y + i;
        out[(size_t)(2 * f + 0) * DIM + k2] = __float2half_rn(th[threadIdx.x][threadIdx.y + i]);
        out[(size_t)(2 * f + 1) * DIM + k2] = __float2half_rn(tg[threadIdx.x][threadIdx.y + i]);
    }
}

// -------- transpose fp32 [R][C] -> fp16 [C][R] (for Wo) -----------
__global__ void k_transpose_h(const float* __restrict__ in, __half* __restrict__ out,
                              int R, int C)
{
    __shared__ float t[32][33];
    int x  = blockIdx.x * 32 + threadIdx.x;
    int y0 = blockIdx.y * 32 + threadIdx.y;
    #pragma unroll
    for (int i = 0; i < 32; i += 8)
        t[threadIdx.y + i][threadIdx.x] = in[(size_t)(y0 + i) * C + x];
    __syncthreads();
    int x2 = blockIdx.y * 32 + threadIdx.x;
    #pragma unroll
    for (int i = 0; i < 32; i += 8)
        out[(size_t)(blockIdx.x * 32 + threadIdx.y + i) * R + x2] =
            __float2half_rn(t[threadIdx.x][threadIdx.y + i]);
}

// ================================================================
// Pipelined fp16 GEMM:  C[M, ND] = A[M, KD] @ B[ND, KD]^T
// BM=128, BN=128, BK=32 halves, 4-stage cp.async, 256 threads,
// 2 CTAs/SM, ldmatrix fragment loads, f32 accumulate.
// ================================================================
#define BKH     32                 // halves per K tile
#define RSTR    20                 // 32-bit words per smem row (16 payload + 4 pad)
#define ROWB    (RSTR * 4)         // 80 bytes per row
#define HALF_T  10240              // 128 rows * 80B (per operand)
#define STG_B   (2 * HALF_T)       // 20480 bytes per stage
#define STAGES  4
#define GEMM_SMEM (STAGES * STG_B) // 81920 -> 2 CTAs/SM

template<int KD>
__device__ __forceinline__ void load_stage(char* smem, int s, int k0,
                                           const __half* __restrict__ A,
                                           const __half* __restrict__ B,
                                           int row0, int col0, int tid)
{
    char* sa = smem + s * STG_B;
    char* sb = sa + HALF_T;
    #pragma unroll
    for (int i = 0; i < 2; i++) {              // A: 512 chunks of 16B
        int id = tid + i * 256;
        int row = id >> 2, c = id & 3;
        cp16(sa + row * ROWB + c * 16, A + (size_t)(row0 + row) * KD + k0 + c * 8);
    }
    #pragma unroll
    for (int i = 0; i < 2; i++) {              // B: 512 chunks of 16B
        int id = tid + i * 256;
        int row = id >> 2, c = id & 3;
        cp16(sb + row * ROWB + c * 16, B + (size_t)(col0 + row) * KD + k0 + c * 8);
    }
}

__device__ __forceinline__ void compute_stage(uint32_t sbase, int s,
                                              float (&acc)[4][4][4],
                                              int wm, int wn, int lane)
{
    const uint32_t sa = sbase + s * STG_B;
    const uint32_t sb = sa + HALF_T;
    const int arow  = lane & 15;
    const int achk  = (lane >> 4) * 16;
    const int brow  = (lane & 7) + ((lane >> 4) & 1) * 8;
    const int bchk  = ((lane >> 3) & 1) * 16;

    #pragma unroll
    for (int kk = 0; kk < 2; kk++) {           // two k16 groups, 32B apart
        uint32_t af[4][4];
        #pragma unroll
        for (int mt = 0; mt < 4; mt++) {
            uint32_t a = sa + (wm * 64 + mt * 16 + arow) * ROWB + achk + kk * 32;
            ldsm4(af[mt][0], af[mt][1], af[mt][2], af[mt][3], a);
        }
        uint32_t bf[4][2];
        #pragma unroll
        for (int p = 0; p < 2; p++) {
            uint32_t a = sb + (wn * 32 + p * 16 + brow) * ROWB + bchk + kk * 32;
            ldsm4(bf[2 * p][0], bf[2 * p][1], bf[2 * p + 1][0], bf[2 * p + 1][1], a);
        }
        #pragma unroll
        for (int mt = 0; mt < 4; mt++)
            #pragma unroll
            for (int nt = 0; nt < 4; nt++)
                mma_f16(acc[mt][nt][0], acc[mt][nt][1],
                        acc[mt][nt][2], acc[mt][nt][3],
                        af[mt][0], af[mt][1], af[mt][2], af[mt][3],
                        bf[nt][0], bf[nt][1]);
    }
}

template<int KD, int ND, typename OutT>
__global__ void __launch_bounds__(256, 2)
k_gemm(const __half* __restrict__ A, const __half* __restrict__ B,
       OutT* __restrict__ C)
{
    extern __shared__ char smem[];
    const uint32_t sbase = (uint32_t)__cvta_generic_to_shared(smem);

    const int tid  = threadIdx.x;
    const int lane = tid & 31;
    const int wid  = tid >> 5;
    const int wm   = wid & 1;     // 0..1  (M, 64 rows each)
    const int wn   = wid >> 1;    // 0..3  (N, 32 cols each)

    const int row0 = blockIdx.x * 128;
    const int col0 = blockIdx.y * 128;

    float acc[4][4][4];
    #pragma unroll
    for (int a = 0; a < 4; a++)
        #pragma unroll
        for (int b = 0; b < 4; b++)
            #pragma unroll
            for (int c = 0; c < 4; c++) acc[a][b][c] = 0.0f;

    #pragma unroll
    for (int s = 0; s < STAGES - 1; s++) {
        load_stage<KD>(smem, s, s * BKH, A, B, row0, col0, tid);
        cp_commit();
    }
    cp_wait<STAGES - 2>();
    __syncthreads();

    const int KT = KD / BKH;
    int rs = 0, ws = STAGES - 1;
    for (int kt = 0; kt < KT; kt++) {
        int kn = kt + STAGES - 1;
        if (kn < KT)
            load_stage<KD>(smem, ws, kn * BKH, A, B, row0, col0, tid);
        cp_commit();
        compute_stage(sbase, rs, acc, wm, wn, lane);
        cp_wait<STAGES - 2>();
        __syncthreads();
        rs = (rs + 1 == STAGES) ? 0 : rs + 1;
        ws = (ws + 1 == STAGES) ? 0 : ws + 1;
    }

    // epilogue
    #pragma unroll
    for (int mt = 0; mt < 4; mt++) {
        #pragma unroll
        for (int nt = 0; nt < 4; nt++) {
            int r = row0 + wm * 64 + mt * 16 + (lane >> 2);
            int c = col0 + wn * 32 + nt * 8 + (lane & 3) * 2;
            #pragma unroll
            for (int half = 0; half < 2; half++) {
                float w0 = acc[mt][nt][half * 2 + 0];
                float w1 = acc[mt][nt][half * 2 + 1];
                size_t idx = (size_t)(r + half * 8) * ND + c;
                if constexpr (sizeof(OutT) == 2) {
                    *reinterpret_cast<__half2*>(
                        reinterpret_cast<__half*>(C) + idx) = __floats2half2_rn(w0, w1);
                } else {
                    *reinterpret_cast<float2*>(
                        reinterpret_cast<float*>(C) + idx) = make_float2(w0, w1);
                }
            }
        }
    }
}

// ================================================================
// Gating + segmented linear scan over interleaved (hidden,gate) stream
//   e = exp(gate); c = 1/(1+e); z = 1-c; v = z * g(hidden)
//   h_t = c_t * h_{t-1} + v_t
// ================================================================
__device__ __forceinline__ void gating(float hid, float gat, float& c, float& v)
{
    float e = __expf(gat);
    c = 1.0f / (1.0f + e);
    float z = 1.0f - c;
    float g = (hid >= 0.0f) ? (hid + 0.5f) : (1.0f / (1.0f + __expf(-hid)));
    v = z * g;
}

#define HGROW4 (HGROW / 8)         // 384 uint4 per hg row
#define NTH4   (DINNER / 4)        // 384 4-channel threads per (b,seg)

__global__ void k_scan1(const uint4* __restrict__ hg,
                        float* __restrict__ segA, float* __restrict__ segB)
{
    int t   = blockIdx.x * 128 + threadIdx.x;   // 0..383
    int seg = blockIdx.y;
    int b   = blockIdx.z;
    size_t base = (size_t)(b * SEQ + seg * SEGLEN) * HGROW4 + t;
    float A[4] = {1.f, 1.f, 1.f, 1.f};
    float H[4] = {0.f, 0.f, 0.f, 0.f};
    #pragma unroll 8
    for (int i = 0; i < SEGLEN; i++) {
        uint4 u = hg[base];
        const __half2* p = reinterpret_cast<const __half2*>(&u);
        #pragma unroll
        for (int j = 0; j < 4; j++) {
            float2 pv = __half22float2(p[j]);
            float c, v;
            gating(pv.x, pv.y, c, v);
            A[j] *= c;
            H[j] = fmaf(c, H[j], v);
        }
        base += HGROW4;
    }
    int sidx = (b * NSEG + seg) * DINNER + t * 4;
    *reinterpret_cast<float4*>(segA + sidx) = make_float4(A[0], A[1], A[2], A[3]);
    *reinterpret_cast<float4*>(segB + sidx) = make_float4(H[0], H[1], H[2], H[3]);
}

__global__ void k_scan2(const float* __restrict__ segA, const float* __restrict__ segB,
                        float* __restrict__ hin)
{
    int idx = blockIdx.x * 256 + threadIdx.x;
    int b = idx / DINNER;
    int f = idx - b * DINNER;
    float h = 0.0f;
    #pragma unroll
    for (int seg = 0; seg < NSEG; seg++) {
        int sidx = (b * NSEG + seg) * DINNER + f;
        hin[sidx] = h;
        h = fmaf(segA[sidx], h, segB[sidx]);
    }
}

__global__ void k_scan3(const uint4* __restrict__ hg, const float* __restrict__ hin,
                        uint2* __restrict__ hout)
{
    int t   = blockIdx.x * 128 + threadIdx.x;   // 0..383
    int seg = blockIdx.y;
    int b   = blockIdx.z;
    size_t base = (size_t)(b * SEQ + seg * SEGLEN) * HGROW4 + t;
    size_t obase = (size_t)(b * SEQ + seg * SEGLEN) * (DINNER / 4) + t;
    float4 h0 = *reinterpret_cast<const float4*>(
        hin + (b * NSEG + seg) * DINNER + t * 4);
    float H[4] = {h0.x, h0.y, h0.z, h0.w};
    #pragma unroll 8
    for (int i = 0; i < SEGLEN; i++) {
        uint4 u = hg[base];
        const __half2* p = reinterpret_cast<const __half2*>(&u);
        __half2 o[2];
        #pragma unroll
        for (int j = 0; j < 4; j++) {
            float2 pv = __half22float2(p[j]);
            float c, v;
            gating(pv.x, pv.y, c, v);
            H[j] = fmaf(c, H[j], v);
        }
        o[0] = __floats2half2_rn(H[0], H[1]);
        o[1] = __floats2half2_rn(H[2], H[3]);
        uint2 w;
        w.x = *reinterpret_cast<uint32_t*>(&o[0]);
        w.y = *reinterpret_cast<uint32_t*>(&o[1]);
        hout[obase] = w;
        base += HGROW4;
        obase += DINNER / 4;
    }
}

// ================================================================
// launch
// ================================================================
extern "C" void kernel_launch(void* const* d_in, const int* in_sizes, int n_in,
                              void* d_out, int out_size)
{
    const float* x  = (const float*)d_in[0];
    const float* Wh = (const float*)d_in[1];
    const float* Wg = (const float*)d_in[2];
    const float* Wo = (const float*)d_in[3];
    float* out = (float*)d_out;

    __half *hgp, *h, *xh, *whg, *wo;
    float *sa, *sb, *hin;
    cudaGetSymbolAddress((void**)&hgp, g_hg);
    cudaGetSymbolAddress((void**)&h,   g_h);
    cudaGetSymbolAddress((void**)&sa,  g_segA);
    cudaGetSymbolAddress((void**)&sb,  g_segB);
    cudaGetSymbolAddress((void**)&hin, g_hin);
    cudaGetSymbolAddress((void**)&xh,  g_xh);
    cudaGetSymbolAddress((void**)&whg, g_whg);
    cudaGetSymbolAddress((void**)&wo,  g_wo);

    cudaFuncSetAttribute(k_gemm<DIM, HGROW, __half>,
                         cudaFuncAttributeMaxDynamicSharedMemorySize, GEMM_SMEM);
    cudaFuncSetAttribute(k_gemm<DINNER, DIM, float>,
                         cudaFuncAttributeMaxDynamicSharedMemorySize, GEMM_SMEM);

    // 1. convert x to fp16; build interleaved W_hg and transposed W_o
    {
        int n4 = (int)((size_t)MROWS * DIM / 4);
        k_cvt_h<<<(n4 + 255) / 256, 256>>>((const float4*)x, (__half2*)xh, n4);
        dim3 tb(32, 8);
        k_transpose_hg<<<dim3(DINNER / 32, DIM / 32), tb>>>(Wh, Wg, whg);
        k_transpose_h<<<dim3(DIM / 32, DINNER / 32), tb>>>(Wo, wo, DINNER, DIM);
    }

    // 2. fused dual projection: hg = x @ [Wh|Wg] (interleaved cols)
    dim3 gP(MROWS / 128, HGROW / 128);        // 128 x 24
    k_gemm<DIM, HGROW, __half><<<gP, 256, GEMM_SMEM>>>(xh, whg, hgp);

    // 3. segmented scan (gating fused)
    dim3 gS(NTH4 / 128, NSEG, BATCH);         // 3 x 64 x 4
    k_scan1<<<gS, 128>>>((const uint4*)hgp, sa, sb);
    k_scan2<<<(BATCH * DINNER) / 256, 256>>>(sa, sb, hin);
    k_scan3<<<gS, 128>>>((const uint4*)hgp, hin, (uint2*)h);

    // 4. output projection
    dim3 gO(MROWS / 128, DIM / 128);          // 128 x 8
    k_gemm<DINNER, DIM, float><<<gO, 256, GEMM_SMEM>>>(h, wo, out);
}

// round 6
// speedup vs baseline: 2.5724x; 1.0474x over previous
#include <cuda_runtime.h>
#include <cuda_fp16.h>
#include <cstdint>
#include <cstddef>

// ---------------- problem constants ----------------
#define BATCH   4
#define SEQ     4096
#define DIM     1024
#define DINNER  1536
#define MROWS   (BATCH * SEQ)          // 16384
#define HGROW   (2 * DINNER)           // 3072 halves per hg row

#define NSEG    64
#define SEGLEN  (SEQ / NSEG)           // 64

// ---------------- static device scratch ------------
__device__ __half g_hg [(size_t)MROWS * HGROW];   // interleaved (hidden,gate)
__device__ __half g_h  [(size_t)MROWS * DINNER];
__device__ float  g_segA[BATCH * NSEG * DINNER];
__device__ float  g_segB[BATCH * NSEG * DINNER];
__device__ float  g_hin [BATCH * NSEG * DINNER];
__device__ __half g_xh [(size_t)MROWS * DIM];
__device__ __half g_whg[(size_t)HGROW * DIM];     // interleaved transposed weights
__device__ __half g_wo [DIM * DINNER];            // transposed: [DIM][DINNER]

// ---------------- helpers --------------------------
__device__ __forceinline__ void mma_f16(float& d0, float& d1, float& d2, float& d3,
                                        uint32_t a0, uint32_t a1, uint32_t a2, uint32_t a3,
                                        uint32_t b0, uint32_t b1) {
    asm volatile(
        "mma.sync.aligned.m16n8k16.row.col.f32.f16.f16.f32 "
        "{%0,%1,%2,%3},{%4,%5,%6,%7},{%8,%9},{%0,%1,%2,%3};\n"
        : "+f"(d0), "+f"(d1), "+f"(d2), "+f"(d3)
        : "r"(a0), "r"(a1), "r"(a2), "r"(a3), "r"(b0), "r"(b1));
}

__device__ __forceinline__ void ldsm4(uint32_t& r0, uint32_t& r1,
                                      uint32_t& r2, uint32_t& r3, uint32_t a) {
    asm volatile("ldmatrix.sync.aligned.m8n8.x4.shared.b16 {%0,%1,%2,%3}, [%4];"
                 : "=r"(r0), "=r"(r1), "=r"(r2), "=r"(r3) : "r"(a));
}

__device__ __forceinline__ void cp16(void* s, const void* g) {
    uint32_t sa = (uint32_t)__cvta_generic_to_shared(s);
    asm volatile("cp.async.cg.shared.global [%0], [%1], 16;\n" :: "r"(sa), "l"(g));
}
__device__ __forceinline__ void cp_commit() {
    asm volatile("cp.async.commit_group;\n");
}
template<int N> __device__ __forceinline__ void cp_wait() {
    asm volatile("cp.async.wait_group %0;\n" :: "n"(N));
}

// ---------------- convert fp32 -> fp16 ----------------
__global__ void k_cvt_h(const float4* __restrict__ in, __half2* __restrict__ out, int n4)
{
    int i = blockIdx.x * 256 + threadIdx.x;
    if (i < n4) {
        float4 v = in[i];
        out[2 * i + 0] = __floats2half2_rn(v.x, v.y);
        out[2 * i + 1] = __floats2half2_rn(v.z, v.w);
    }
}

// -------- transpose Wh,Wg [DIM][DINNER] f32 -> interleaved [2*DINNER][DIM] f16
__global__ void k_transpose_hg(const float* __restrict__ Wh, const float* __restrict__ Wg,
                               __half* __restrict__ out)
{
    __shared__ float th[32][33], tg[32][33];
    int x  = blockIdx.x * 32 + threadIdx.x;     // f
    int y0 = blockIdx.y * 32 + threadIdx.y;     // k
    #pragma unroll
    for (int i = 0; i < 32; i += 8) {
        th[threadIdx.y + i][threadIdx.x] = Wh[(size_t)(y0 + i) * DINNER + x];
        tg[threadIdx.y + i][threadIdx.x] = Wg[(size_t)(y0 + i) * DINNER + x];
    }
    __syncthreads();
    int k2 = blockIdx.y * 32 + threadIdx.x;     // k
    #pragma unroll
    for (int i = 0; i < 32; i += 8) {
        int f = blockIdx.x * 32 + threadIdx.y + i;
        out[(size_t)(2 * f + 0) * DIM + k2] = __float2half_rn(th[threadIdx.x][threadIdx.y + i]);
        out[(size_t)(2 * f + 1) * DIM + k2] = __float2half_rn(tg[threadIdx.x][threadIdx.y + i]);
    }
}

// -------- transpose fp32 [R][C] -> fp16 [C][R] (for Wo) -----------
__global__ void k_transpose_h(const float* __restrict__ in, __half* __restrict__ out,
                              int R, int C)
{
    __shared__ float t[32][33];
    int x  = blockIdx.x * 32 + threadIdx.x;
    int y0 = blockIdx.y * 32 + threadIdx.y;
    #pragma unroll
    for (int i = 0; i < 32; i += 8)
        t[threadIdx.y + i][threadIdx.x] = in[(size_t)(y0 + i) * C + x];
    __syncthreads();
    int x2 = blockIdx.y * 32 + threadIdx.x;
    #pragma unroll
    for (int i = 0; i < 32; i += 8)
        out[(size_t)(blockIdx.x * 32 + threadIdx.y + i) * R + x2] =
            __float2half_rn(t[threadIdx.x][threadIdx.y + i]);
}

// ================================================================
// Pipelined fp16 GEMM:  C[M, ND] = A[M, KD] @ B[ND, KD]^T
// BM=128, BN=128, BK=32 halves, 5-stage cp.async ring,
// TWO K-tiles consumed per barrier (halved sync frequency),
// 256 threads, 2 CTAs/SM, ldmatrix fragment loads, f32 accumulate.
// ================================================================
#define BKH     32                 // halves per K tile
#define RSTR    20                 // 32-bit words per smem row (16 payload + 4 pad)
#define ROWB    (RSTR * 4)         // 80 bytes per row
#define HALF_T  10240              // 128 rows * 80B (per operand)
#define STG_B   (2 * HALF_T)       // 20480 bytes per stage
#define STAGES  5
#define GEMM_SMEM (STAGES * STG_B) // 102400 -> 2 CTAs/SM

template<int KD>
__device__ __forceinline__ void load_stage(char* smem, int s, int k0,
                                           const __half* __restrict__ A,
                                           const __half* __restrict__ B,
                                           int row0, int col0, int tid)
{
    char* sa = smem + s * STG_B;
    char* sb = sa + HALF_T;
    #pragma unroll
    for (int i = 0; i < 2; i++) {              // A: 512 chunks of 16B
        int id = tid + i * 256;
        int row = id >> 2, c = id & 3;
        cp16(sa + row * ROWB + c * 16, A + (size_t)(row0 + row) * KD + k0 + c * 8);
    }
    #pragma unroll
    for (int i = 0; i < 2; i++) {              // B: 512 chunks of 16B
        int id = tid + i * 256;
        int row = id >> 2, c = id & 3;
        cp16(sb + row * ROWB + c * 16, B + (size_t)(col0 + row) * KD + k0 + c * 8);
    }
}

__device__ __forceinline__ void compute_stage(uint32_t sbase, int s,
                                              float (&acc)[4][4][4],
                                              int wm, int wn, int lane)
{
    const uint32_t sa = sbase + s * STG_B;
    const uint32_t sb = sa + HALF_T;
    const int arow  = lane & 15;
    const int achk  = (lane >> 4) * 16;
    const int brow  = (lane & 7) + ((lane >> 4) & 1) * 8;
    const int bchk  = ((lane >> 3) & 1) * 16;

    #pragma unroll
    for (int kk = 0; kk < 2; kk++) {           // two k16 groups, 32B apart
        uint32_t af[4][4];
        #pragma unroll
        for (int mt = 0; mt < 4; mt++) {
            uint32_t a = sa + (wm * 64 + mt * 16 + arow) * ROWB + achk + kk * 32;
            ldsm4(af[mt][0], af[mt][1], af[mt][2], af[mt][3], a);
        }
        uint32_t bf[4][2];
        #pragma unroll
        for (int p = 0; p < 2; p++) {
            uint32_t a = sb + (wn * 32 + p * 16 + brow) * ROWB + bchk + kk * 32;
            ldsm4(bf[2 * p][0], bf[2 * p][1], bf[2 * p + 1][0], bf[2 * p + 1][1], a);
        }
        #pragma unroll
        for (int mt = 0; mt < 4; mt++)
            #pragma unroll
            for (int nt = 0; nt < 4; nt++)
                mma_f16(acc[mt][nt][0], acc[mt][nt][1],
                        acc[mt][nt][2], acc[mt][nt][3],
                        af[mt][0], af[mt][1], af[mt][2], af[mt][3],
                        bf[nt][0], bf[nt][1]);
    }
}

template<int KD, int ND, typename OutT>
__global__ void __launch_bounds__(256, 2)
k_gemm(const __half* __restrict__ A, const __half* __restrict__ B,
       OutT* __restrict__ C)
{
    extern __shared__ char smem[];
    const uint32_t sbase = (uint32_t)__cvta_generic_to_shared(smem);

    const int tid  = threadIdx.x;
    const int lane = tid & 31;
    const int wid  = tid >> 5;
    const int wm   = wid & 1;     // 0..1  (M, 64 rows each)
    const int wn   = wid >> 1;    // 0..3  (N, 32 cols each)

    const int row0 = blockIdx.x * 128;
    const int col0 = blockIdx.y * 128;

    float acc[4][4][4];
    #pragma unroll
    for (int a = 0; a < 4; a++)
        #pragma unroll
        for (int b = 0; b < 4; b++)
            #pragma unroll
            for (int c = 0; c < 4; c++) acc[a][b][c] = 0.0f;

    // prologue: tiles 0,1,2 into stages 0,1,2 (one group per tile)
    #pragma unroll
    for (int s = 0; s < 3; s++) {
        load_stage<KD>(smem, s, s * BKH, A, B, row0, col0, tid);
        cp_commit();
    }

    const int KT = KD / BKH;      // 32 or 48 (always even)
    const int P  = KT / 2;

    int rs = 0;                   // stage of tile 2i
    int ws = 3;                   // stage of tile 2i+3
    for (int i = 0; i < P; i++) {
        cp_wait<1>();             // tiles 2i, 2i+1 arrived
        __syncthreads();          // visible to all; prior compute done

        int t0 = 2 * i + 3, t1 = 2 * i + 4;
        if (t0 < KT) load_stage<KD>(smem, ws, t0 * BKH, A, B, row0, col0, tid);
        cp_commit();              // unconditional: keeps group counts aligned
        int ws2 = (ws + 1 == STAGES) ? 0 : ws + 1;
        if (t1 < KT) load_stage<KD>(smem, ws2, t1 * BKH, A, B, row0, col0, tid);
        cp_commit();
        ws = (ws2 + 1 == STAGES) ? 0 : ws2 + 1;

        compute_stage(sbase, rs, acc, wm, wn, lane);
        int rs2 = (rs + 1 == STAGES) ? 0 : rs + 1;
        compute_stage(sbase, rs2, acc, wm, wn, lane);
        rs = (rs2 + 1 == STAGES) ? 0 : rs2 + 1;
    }

    // epilogue
    #pragma unroll
    for (int mt = 0; mt < 4; mt++) {
        #pragma unroll
        for (int nt = 0; nt < 4; nt++) {
            int r = row0 + wm * 64 + mt * 16 + (lane >> 2);
            int c = col0 + wn * 32 + nt * 8 + (lane & 3) * 2;
            #pragma unroll
            for (int half = 0; half < 2; half++) {
                float w0 = acc[mt][nt][half * 2 + 0];
                float w1 = acc[mt][nt][half * 2 + 1];
                size_t idx = (size_t)(r + half * 8) * ND + c;
                if constexpr (sizeof(OutT) == 2) {
                    *reinterpret_cast<__half2*>(
                        reinterpret_cast<__half*>(C) + idx) = __floats2half2_rn(w0, w1);
                } else {
                    *reinterpret_cast<float2*>(
                        reinterpret_cast<float*>(C) + idx) = make_float2(w0, w1);
                }
            }
        }
    }
}

// ================================================================
// Gating + segmented linear scan over interleaved (hidden,gate) stream
//   e = exp(gate); c = 1/(1+e); z = 1-c; v = z * g(hidden)
//   h_t = c_t * h_{t-1} + v_t
// ================================================================
__device__ __forceinline__ void gating(float hid, float gat, float& c, float& v)
{
    float e = __expf(gat);
    c = 1.0f / (1.0f + e);
    float z = 1.0f - c;
    float g = (hid >= 0.0f) ? (hid + 0.5f) : (1.0f / (1.0f + __expf(-hid)));
    v = z * g;
}

#define HGROW4 (HGROW / 8)         // 384 uint4 per hg row
#define NTH4   (DINNER / 4)        // 384 4-channel threads per (b,seg)

__global__ void k_scan1(const uint4* __restrict__ hg,
                        float* __restrict__ segA, float* __restrict__ segB)
{
    int t   = blockIdx.x * 128 + threadIdx.x;   // 0..383
    int seg = blockIdx.y;
    int b   = blockIdx.z;
    size_t base = (size_t)(b * SEQ + seg * SEGLEN) * HGROW4 + t;
    float A[4] = {1.f, 1.f, 1.f, 1.f};
    float H[4] = {0.f, 0.f, 0.f, 0.f};
    #pragma unroll 8
    for (int i = 0; i < SEGLEN; i++) {
        uint4 u = hg[base];
        const __half2* p = reinterpret_cast<const __half2*>(&u);
        #pragma unroll
        for (int j = 0; j < 4; j++) {
            float2 pv = __half22float2(p[j]);
            float c, v;
            gating(pv.x, pv.y, c, v);
            A[j] *= c;
            H[j] = fmaf(c, H[j], v);
        }
        base += HGROW4;
    }
    int sidx = (b * NSEG + seg) * DINNER + t * 4;
    *reinterpret_cast<float4*>(segA + sidx) = make_float4(A[0], A[1], A[2], A[3]);
    *reinterpret_cast<float4*>(segB + sidx) = make_float4(H[0], H[1], H[2], H[3]);
}

__global__ void k_scan2(const float* __restrict__ segA, const float* __restrict__ segB,
                        float* __restrict__ hin)
{
    int idx = blockIdx.x * 256 + threadIdx.x;
    int b = idx / DINNER;
    int f = idx - b * DINNER;
    float h = 0.0f;
    #pragma unroll
    for (int seg = 0; seg < NSEG; seg++) {
        int sidx = (b * NSEG + seg) * DINNER + f;
        hin[sidx] = h;
        h = fmaf(segA[sidx], h, segB[sidx]);
    }
}

__global__ void k_scan3(const uint4* __restrict__ hg, const float* __restrict__ hin,
                        uint2* __restrict__ hout)
{
    int t   = blockIdx.x * 128 + threadIdx.x;   // 0..383
    int seg = blockIdx.y;
    int b   = blockIdx.z;
    size_t base = (size_t)(b * SEQ + seg * SEGLEN) * HGROW4 + t;
    size_t obase = (size_t)(b * SEQ + seg * SEGLEN) * (DINNER / 4) + t;
    float4 h0 = *reinterpret_cast<const float4*>(
        hin + (b * NSEG + seg) * DINNER + t * 4);
    float H[4] = {h0.x, h0.y, h0.z, h0.w};
    #pragma unroll 8
    for (int i = 0; i < SEGLEN; i++) {
        uint4 u = hg[base];
        const __half2* p = reinterpret_cast<const __half2*>(&u);
        __half2 o[2];
        #pragma unroll
        for (int j = 0; j < 4; j++) {
            float2 pv = __half22float2(p[j]);
            float c, v;
            gating(pv.x, pv.y, c, v);
            H[j] = fmaf(c, H[j], v);
        }
        o[0] = __floats2half2_rn(H[0], H[1]);
        o[1] = __floats2half2_rn(H[2], H[3]);
        uint2 w;
        w.x = *reinterpret_cast<uint32_t*>(&o[0]);
        w.y = *reinterpret_cast<uint32_t*>(&o[1]);
        hout[obase] = w;
        base += HGROW4;
        obase += DINNER / 4;
    }
}

// ================================================================
// launch
// ================================================================
extern "C" void kernel_launch(void* const* d_in, const int* in_sizes, int n_in,
                              void* d_out, int out_size)
{
    const float* x  = (const float*)d_in[0];
    const float* Wh = (const float*)d_in[1];
    const float* Wg = (const float*)d_in[2];
    const float* Wo = (const float*)d_in[3];
    float* out = (float*)d_out;

    __half *hgp, *h, *xh, *whg, *wo;
    float *sa, *sb, *hin;
    cudaGetSymbolAddress((void**)&hgp, g_hg);
    cudaGetSymbolAddress((void**)&h,   g_h);
    cudaGetSymbolAddress((void**)&sa,  g_segA);
    cudaGetSymbolAddress((void**)&sb,  g_segB);
    cudaGetSymbolAddress((void**)&hin, g_hin);
    cudaGetSymbolAddress((void**)&xh,  g_xh);
    cudaGetSymbolAddress((void**)&whg, g_whg);
    cudaGetSymbolAddress((void**)&wo,  g_wo);

    cudaFuncSetAttribute(k_gemm<DIM, HGROW, __half>,
                         cudaFuncAttributeMaxDynamicSharedMemorySize, GEMM_SMEM);
    cudaFuncSetAttribute(k_gemm<DINNER, DIM, float>,
                         cudaFuncAttributeMaxDynamicSharedMemorySize, GEMM_SMEM);

    // 1. convert x to fp16; build interleaved W_hg and transposed W_o
    {
        int n4 = (int)((size_t)MROWS * DIM / 4);
        k_cvt_h<<<(n4 + 255) / 256, 256>>>((const float4*)x, (__half2*)xh, n4);
        dim3 tb(32, 8);
        k_transpose_hg<<<dim3(DINNER / 32, DIM / 32), tb>>>(Wh, Wg, whg);
        k_transpose_h<<<dim3(DIM / 32, DINNER / 32), tb>>>(Wo, wo, DINNER, DIM);
    }

    // 2. fused dual projection: hg = x @ [Wh|Wg] (interleaved cols)
    dim3 gP(MROWS / 128, HGROW / 128);        // 128 x 24
    k_gemm<DIM, HGROW, __half><<<gP, 256, GEMM_SMEM>>>(xh, whg, hgp);

    // 3. segmented scan (gating fused)
    dim3 gS(NTH4 / 128, NSEG, BATCH);         // 3 x 64 x 4
    k_scan1<<<gS, 128>>>((const uint4*)hgp, sa, sb);
    k_scan2<<<(BATCH * DINNER) / 256, 256>>>(sa, sb, hin);
    k_scan3<<<gS, 128>>>((const uint4*)hgp, hin, (uint2*)h);

    // 4. output projection
    dim3 gO(MROWS / 128, DIM / 128);          // 128 x 8
    k_gemm<DINNER, DIM, float><<<gO, 256, GEMM_SMEM>>>(h, wo, out);
}